// round 10
// baseline (speedup 1.0000x reference)
#include <cuda_runtime.h>
#include <cuda_fp16.h>
#include <cstdint>

#define NRELM 20000
#define NEDGEM 640000

// Scratch (allocation-free rule: __device__ globals)
__device__ float g_Ph[NRELM * 128];                 // fp32, read once per relation
__device__ uint4 g_PM[NRELM * 32];                  // fp16 interleaved: per lane 4xPt | 4xM
__device__ int2  g_node[NEDGEM];                    // {next_edge, tail | bin<<20}
__device__ int   g_head[NRELM];                     // linked-list heads
__device__ int   g_is64;

__device__ __forceinline__ float lrelu(float x) {
    return x >= 0.f ? x : 0.2f * x;
}

// ---- packed f32x2 helpers (FFMA2: ptxas never auto-fuses; PTX-only) ----
__device__ __forceinline__ unsigned long long pk2(float x, float y) {
    unsigned long long r;
    asm("mov.b64 %0, {%1, %2};" : "=l"(r) : "f"(x), "f"(y));
    return r;
}
__device__ __forceinline__ void fma2(unsigned long long& d, unsigned long long a,
                                     unsigned long long b) {
    asm("fma.rn.f32x2 %0, %1, %2, %3;" : "=l"(d) : "l"(a), "l"(b), "l"(d));
}
__device__ __forceinline__ void unpk2(float& x, float& y, unsigned long long v) {
    asm("mov.b64 {%0, %1}, %2;" : "=f"(x), "=f"(y) : "l"(v));
}

// Launch 1: reset list heads + detect int64-vs-int32 triplets (parallel warp).
__global__ void k_init(const int* __restrict__ t, int nrel) {
    int i = blockIdx.x * blockDim.x + threadIdx.x;
    if (i < nrel) g_head[i] = -1;
    if (blockIdx.x == 0 && threadIdx.x < 32) {
        int any = 0;
        #pragma unroll
        for (int k = 0; k < 8; k++) any |= t[2 * (threadIdx.x * 8 + k) + 1];
        unsigned nz = __ballot_sync(0xffffffffu, any != 0);
        if (threadIdx.x == 0) g_is64 = (nz == 0u) ? 1 : 0;
    }
}

// Launch 2: heterogeneous kernel, 512 threads/block.
//  - "pre" blocks (1 of every 3): projection tables, 32 relations/block
//    (4 halves x 8 rels), packed f32x2 FMAs, weights staged via smem d-tiles.
//  - "link" blocks (2 of every 3): build per-head linked lists (atomicExch).
#define TD 16           // d-tile
#define WPAD 129        // wsm row stride (129 % 32 == 1 -> conflict-free reads)
__global__ void __launch_bounds__(512) k_prelink(
        const float* __restrict__ emb,
        const float* __restrict__ wA, const float* __restrict__ bA,
        const float* __restrict__ wG, const float* __restrict__ bG,
        const void* __restrict__ trip,
        int nrel, int nedge, int npre) {
    const int b = blockIdx.x;
    const bool is_pre = ((b % 3) == 0) && (b / 3 < npre);

    if (!is_pre) {
        // ---------- LINK ROLE ----------
        const int pre_before = min((b + 2) / 3, npre);
        const int linkid = b - pre_before;
        const int e = linkid * 512 + threadIdx.x;
        if (e >= nedge) return;
        int h, tl, bn;
        if (g_is64) {
            const long long* T = (const long long*)trip;
            h  = (int)T[(size_t)3 * e];
            tl = (int)T[(size_t)3 * e + 1];
            bn = (int)T[(size_t)3 * e + 2];
        } else {
            const int* T = (const int*)trip;
            h  = T[(size_t)3 * e];
            tl = T[(size_t)3 * e + 1];
            bn = T[(size_t)3 * e + 2];
        }
        int prev = atomicExch(&g_head[h], e);
        g_node[e] = make_int2(prev, tl | (bn << 20));
        return;
    }

    // ---------- PRE ROLE ----------
    __shared__ unsigned long long sep[16 * 128];       // 4 halves x 4 pairs x 128 dims
    __shared__ float wsmh[TD * WPAD];                  // wh tile [dk][t]
    __shared__ float wsmt[TD * WPAD];                  // wt tile
    __shared__ float wsmg[TD * WPAD];                  // wg tile
    const int preid = b / 3;
    const int tid = threadIdx.x;
    const int half = tid >> 7;          // 0..3: which 8-relation group
    const int t = tid & 127;            // output dim 0..127
    const int r0 = preid * 32 + half * 8;
    unsigned long long* sh = sep + half * 512;

    #pragma unroll
    for (int p = 0; p < 4; p++) {
        int ra = r0 + 2 * p, rb = ra + 1;
        float ea = (ra < nrel) ? emb[(size_t)ra * 128 + t] : 0.f;
        float eb = (rb < nrel) ? emb[(size_t)rb * 128 + t] : 0.f;
        sh[p * 128 + t] = pk2(ea, eb);
    }

    unsigned long long ah[4], at[4], am[4];
    #pragma unroll
    for (int p = 0; p < 4; p++) { ah[p] = 0ull; at[p] = 0ull; am[p] = 0ull; }

    // staging assignment: tid -> (row = tid/4, colgroup = tid%4), 1 float4/table
    const int srow = tid >> 2;
    const int scg  = (tid & 3) * 4;

    for (int d0 = 0; d0 < 128; d0 += TD) {
        __syncthreads();   // previous tile fully consumed
        {
            float4 h4 = *(const float4*)(wA + (size_t)srow * 256 + d0 + scg);
            float4 t4 = *(const float4*)(wA + (size_t)srow * 256 + 128 + d0 + scg);
            float4 g4 = *(const float4*)(wG + (size_t)srow * 128 + d0 + scg);
            #pragma unroll
            for (int j = 0; j < 4; j++) {
                wsmh[(scg + j) * WPAD + srow] = (&h4.x)[j];
                wsmt[(scg + j) * WPAD + srow] = (&t4.x)[j];
                wsmg[(scg + j) * WPAD + srow] = (&g4.x)[j];
            }
        }
        __syncthreads();

        #pragma unroll
        for (int dk = 0; dk < TD; dk++) {
            unsigned long long whb, wtb, wgb;
            {
                float wv = wsmh[dk * WPAD + t];
                whb = pk2(wv, wv);
                wv = wsmt[dk * WPAD + t];
                wtb = pk2(wv, wv);
                wv = wsmg[dk * WPAD + t];
                wgb = pk2(wv, wv);
            }
            #pragma unroll
            for (int p = 0; p < 4; p++) {
                unsigned long long a2 = sh[p * 128 + d0 + dk];
                fma2(ah[p], a2, whb);
                fma2(at[p], a2, wtb);
                fma2(am[p], a2, wgb);
            }
        }
    }

    const float bb = bA[t];
    const float bg = bG[t];
    const int g = t >> 2, j = t & 3;   // PM packing: 16B group g = [Pt 4 halves | M 4 halves]
    __half* PMH = (__half*)g_PM;
    #pragma unroll
    for (int p = 0; p < 4; p++) {
        int ra = r0 + 2 * p, rb = ra + 1;
        float hx, hy, tx, ty, mx, my;
        unpk2(hx, hy, ah[p]);
        unpk2(tx, ty, at[p]);
        unpk2(mx, my, am[p]);
        if (ra < nrel) {
            g_Ph[(size_t)ra * 128 + t] = hx;
            PMH[(size_t)ra * 256 + g * 8 + j]     = __float2half_rn(tx + bb);
            PMH[(size_t)ra * 256 + g * 8 + 4 + j] = __float2half_rn(mx + bg);
        }
        if (rb < nrel) {
            g_Ph[(size_t)rb * 128 + t] = hy;
            PMH[(size_t)rb * 256 + g * 8 + j]     = __float2half_rn(ty + bb);
            PMH[(size_t)rb * 256 + g * 8 + 4 + j] = __float2half_rn(my + bg);
        }
    }
}

__device__ __forceinline__ float2 h2f(unsigned u) {
    __half2 h = *(__half2*)&u;
    return __half22float2(h);
}

// Launch 3: fused attention+softmax+aggregation.
// One warp per relation; lane l covers dims 4l..4l+3 (head = l>>2).
__global__ void __launch_bounds__(256) k_fused(
        const float* __restrict__ attn_bin,
        const float* __restrict__ attn_vec,
        float* __restrict__ out, int nrel) {
    __shared__ float sbin[80];  // lrelu(attn_bin) [bin*8 + head]
    const int t = threadIdx.x;
    if (t < 80) {
        float b = attn_bin[t];
        sbin[t] = (b >= 0.f) ? b : 0.2f * b;
    }
    __syncthreads();

    const int lane = t & 31;
    const int r = (blockIdx.x * blockDim.x + t) >> 5;
    if (r >= nrel) return;
    const int hh = lane >> 2;

    const float4 vec4 = *(const float4*)(attn_vec + 4 * lane);
    const float4 ph   = *(const float4*)(g_Ph + (size_t)r * 128 + 4 * lane);

    float4 acc = make_float4(0.f, 0.f, 0.f, 0.f);
    float vsum = 0.f;

    int e = g_head[r];
    int2 nd = make_int2(-1, 0);
    if (e >= 0) nd = g_node[e];

    while (e >= 0) {
        const int enext = nd.x;
        const int pk = nd.y;
        // prefetch next node (the only true dependency chain)
        int2 nd2 = nd;
        if (enext >= 0) nd2 = g_node[enext];

        const int tl = pk & 0xFFFFF;
        const int bn = pk >> 20;
        const uint4 pm = g_PM[(size_t)tl * 32 + lane];

        float2 p01 = h2f(pm.x), p23 = h2f(pm.y);
        float2 m01 = h2f(pm.z), m23 = h2f(pm.w);

        float x0 = lrelu(ph.x + p01.x);
        float x1 = lrelu(ph.y + p01.y);
        float x2 = lrelu(ph.z + p23.x);
        float x3 = lrelu(ph.w + p23.y);
        float sd = fmaf(x0, vec4.x, fmaf(x1, vec4.y, fmaf(x2, vec4.z, x3 * vec4.w)));
        sd += __shfl_xor_sync(0xffffffffu, sd, 1);
        sd += __shfl_xor_sync(0xffffffffu, sd, 2);

        float v = __expf(sd + sbin[bn * 8 + hh]);
        acc.x = fmaf(v, m01.x, acc.x);
        acc.y = fmaf(v, m01.y, acc.y);
        acc.z = fmaf(v, m23.x, acc.z);
        acc.w = fmaf(v, m23.y, acc.w);
        vsum += v;

        e = enext;
        nd = nd2;
    }

    float inv = 1.f / (vsum + 1e-16f);
    float4 o = make_float4(acc.x * inv, acc.y * inv, acc.z * inv, acc.w * inv);
    *(float4*)(out + (size_t)r * 128 + 4 * lane) = o;
}

extern "C" void kernel_launch(void* const* d_in, const int* in_sizes, int n_in,
                              void* d_out, int out_size) {
    const float* emb = (const float*)d_in[0];
    const void*  trip = d_in[1];
    const float* wA  = (const float*)d_in[2];
    const float* bA  = (const float*)d_in[3];
    const float* bin = (const float*)d_in[4];
    const float* vec = (const float*)d_in[5];
    const float* wG  = (const float*)d_in[6];
    const float* bG  = (const float*)d_in[7];
    float* out = (float*)d_out;

    int nrel  = in_sizes[0] / 128;
    int nedge = in_sizes[1] / 3;

    int npre  = (nrel + 31) / 32;
    int nlink = (nedge + 511) / 512;

    k_init<<<(nrel + 255) / 256, 256>>>((const int*)trip, nrel);
    k_prelink<<<npre + nlink, 512>>>(emb, wA, bA, wG, bG, trip, nrel, nedge, npre);
    k_fused<<<(nrel * 32 + 255) / 256, 256>>>(bin, vec, out, nrel);
}